// round 8
// baseline (speedup 1.0000x reference)
#include <cuda_runtime.h>
#include <cuda_bf16.h>
#include <stdint.h>
#include <math.h>

// ---------------- problem constants ----------------
#define NI    10000
#define TWOD  256
#define D3    384
#define NW    1152           // 3*D3 : [key | val | qproj]
#define B_    1024
#define L_    100
#define NCH   40             // chunks for deterministic fp32 column sums
#define CROWS 250            // NI / NCH
#define KP2   10240          // NI padded to 256-multiple (gram split-K)

// ---------------- scratch ----------------
__device__ __align__(16) __nv_bfloat16  g_qb[NI * TWOD];         // q bf16 (region GEMM A)
__device__ __align__(16) __nv_bfloat16  g_qT[TWOD * KP2];        // q^T bf16, zero-padded
__device__ __align__(16) float          g_cpart[NCH * TWOD];
__device__ __align__(16) float          g_colsum[TWOD];
__device__ __align__(16) float          g_ksum16[TWOD];
__device__ __align__(16) float          g_gpart[NCH * TWOD * TWOD];  // Gram partials
__device__ __align__(16) __nv_bfloat16  g_GsT[TWOD * TWOD];      // GsT[n][e] = Gs[e][n]
__device__ __align__(16) float          g_rs[NI];
__device__ __align__(16) float          g_cat[NI * D3];          // [emb_item | region] fp32
__device__ __align__(16) __nv_bfloat16  g_ch[NI * D3];
__device__ __align__(16) __nv_bfloat16  g_cl[NI * D3];
__device__ __align__(16) __nv_bfloat16  g_wh[NW * D3];
__device__ __align__(16) __nv_bfloat16  g_wl[NW * D3];
__device__ __align__(16) float          g_bias[NW];
__device__ __align__(16) float          g_kvq[NI * NW];          // item table (46 MB)

// ---------------- helpers ----------------
__device__ __forceinline__ uint32_t smem_u32(const void* p) {
    uint32_t a;
    asm("{ .reg .u64 t; cvta.to.shared.u64 t, %1; cvt.u32.u64 %0, t; }" : "=r"(a) : "l"(p));
    return a;
}
__device__ __forceinline__ uint32_t pack_bf2(float a, float b) {
    __nv_bfloat162 t = __floats2bfloat162_rn(a, b);
    return *(uint32_t*)&t;
}

#define LDM4(r, a) \
    asm volatile("ldmatrix.sync.aligned.m8n8.x4.shared.b16 {%0,%1,%2,%3}, [%4];" \
        : "=r"((r)[0]), "=r"((r)[1]), "=r"((r)[2]), "=r"((r)[3]) : "r"(a))

#define MMA16816(d, a, b0, b1) \
    asm volatile("mma.sync.aligned.m16n8k16.row.col.f32.bf16.bf16.f32 " \
        "{%0,%1,%2,%3}, {%4,%5,%6,%7}, {%8,%9}, {%0,%1,%2,%3};" \
        : "+f"((d)[0]), "+f"((d)[1]), "+f"((d)[2]), "+f"((d)[3]) \
        : "r"((a)[0]), "r"((a)[1]), "r"((a)[2]), "r"((a)[3]), "r"(b0), "r"(b1))

#define CP16(dst, src, sz) \
    asm volatile("cp.async.cg.shared.global [%0], [%1], 16, %2;" \
        :: "r"(dst), "l"(src), "r"(sz))
#define CP_COMMIT() asm volatile("cp.async.commit_group;" ::: "memory")
#define CP_WAIT(n)  asm volatile("cp.async.wait_group %0;" :: "n"(n) : "memory")

#define TILE_B 10240   // 128 rows x 32 bf16, pitch 80 B (conflict-free ldmatrix)

__device__ __forceinline__ void cp_tile(const __nv_bfloat16* __restrict__ src, int ld,
                                        int row0, int maxR, int k0, uint32_t smDst, int tid) {
    int r = tid >> 1, h = tid & 1;
    int grow = row0 + r;
    const __nv_bfloat16* g = src + (size_t)grow * ld + k0 + h * 16;
    uint32_t dst = smDst + (uint32_t)(r * 80 + h * 32);
    int sz = (grow < maxR) ? 16 : 0;
    CP16(dst, g, sz);
    CP16(dst + 16, g + 8, sz);
}

// ---------------- stage 1: qb bf16 ----------------
__global__ void build_qb_kernel(const float* __restrict__ ein, const float* __restrict__ eout) {
    int idx = blockIdx.x * 256 + threadIdx.x;                 // over NI*128
    if (idx >= NI * 128) return;
    int i = idx >> 7, d = idx & 127;
    g_qb[i * TWOD + d]       = __float2bfloat16(ein[idx]);
    g_qb[i * TWOD + 128 + d] = __float2bfloat16(eout[idx]);
}

// ---------------- stage 2: q^T bf16 (tiled transpose, zero pad) ----------------
__global__ void qT_kernel(const float* __restrict__ ein, const float* __restrict__ eout) {
    __shared__ float tile[32][33];
    int k0 = blockIdx.x * 32, c0 = blockIdx.y * 32;           // grid (320, 8)
    const float* src = (c0 < 128) ? ein : eout;
    int cb = (c0 < 128) ? c0 : c0 - 128;
    #pragma unroll
    for (int i = 0; i < 4; ++i) {
        int k = k0 + threadIdx.y + 8 * i;
        tile[threadIdx.y + 8 * i][threadIdx.x] =
            (k < NI) ? src[(size_t)k * 128 + cb + threadIdx.x] : 0.f;
    }
    __syncthreads();
    #pragma unroll
    for (int i = 0; i < 4; ++i) {
        int c = c0 + threadIdx.y + 8 * i;
        g_qT[(size_t)c * KP2 + k0 + threadIdx.x] =
            __float2bfloat16(tile[threadIdx.x][threadIdx.y + 8 * i]);
    }
}

// ---------------- stage 3: exact fp32 column sums ----------------
__global__ void colsum_part_kernel(const float* __restrict__ ein, const float* __restrict__ eout) {
    int c = threadIdx.x, z = blockIdx.x;                      // grid NCH, block 256
    const float* src = (c < 128) ? ein : eout;
    int cb = (c < 128) ? c : c - 128;
    float s = 0.f;
    for (int k = z * CROWS; k < z * CROWS + CROWS; ++k) s += src[(size_t)k * 128 + cb];
    g_cpart[z * TWOD + c] = s;
}
__global__ void colsum_fin_kernel() {
    __shared__ float cs[TWOD];
    int n = threadIdx.x;
    float s = 0.f;
    for (int z = 0; z < NCH; ++z) s += g_cpart[z * TWOD + n];
    g_colsum[n] = s;
    cs[n] = s;
    __syncthreads();
    g_ksum16[n] = cs[(n + 128) & 255] * 0.0625f;              // k is 128-rotation of q
}

// ---------------- stage 4: per-row denominator ----------------
__global__ void rs_kernel(const float* __restrict__ ein, const float* __restrict__ eout) {
    __shared__ float sk[TWOD];
    int tid = threadIdx.x;
    sk[tid] = g_ksum16[tid];
    __syncthreads();
    int w = tid >> 5, lane = tid & 31;
    int i = blockIdx.x * 8 + w;                               // grid 1250
    if (i >= NI) return;
    float s = 0.f;
    #pragma unroll
    for (int c = lane; c < 128; c += 32)
        s += ein[(size_t)i * 128 + c] * sk[c] + eout[(size_t)i * 128 + c] * sk[128 + c];
    #pragma unroll
    for (int o = 16; o > 0; o >>= 1) s += __shfl_xor_sync(0xFFFFFFFFu, s, o);
    if (lane == 0) g_rs[i] = 1.0f / (10000.0f + s);
}

// ---------------- unified mma GEMM ----------------
// C[m,n] = sum_k A[m,k]*B[n,k].  NS==3: + Ahi*Blo + Alo*Bhi.
// EPI 0: Cf[m*ldc+n] = acc + aux1[n]                      (KVQ)
// EPI 1: Cf[z*zs + m*ldc+n] = acc                         (gram split-K partials)
// EPI 2: v = (aux1[n]+acc)*aux2[m] -> g_cat[m*D3+128+n], g_ch, g_cl   (region)
template <int EPI, int NS>
__global__ __launch_bounds__(256) void mma_gemm(
    int M, int N, int K, int KCHUNK,
    const __nv_bfloat16* __restrict__ A, const __nv_bfloat16* __restrict__ Al, int lda,
    const __nv_bfloat16* __restrict__ B, const __nv_bfloat16* __restrict__ Bl, int ldb,
    float* __restrict__ Cf, int ldc, size_t zs,
    const float* __restrict__ aux1, const float* __restrict__ aux2)
{
    extern __shared__ __align__(128) char dsm[];
    const int tid = threadIdx.x;
    const int warp = tid >> 5, lane = tid & 31;
    const int wm = warp >> 2, wn = warp & 3;
    const int m0 = blockIdx.y * 128, n0 = blockIdx.x * 128;
    const int nT = (NS == 3) ? 4 : 2;
    const uint32_t smBase = smem_u32(dsm);
    const int kbase = blockIdx.z * KCHUNK;
    const int nc = KCHUNK >> 5;

    float acc[4][4][4];
    #pragma unroll
    for (int i = 0; i < 4; ++i)
        #pragma unroll
        for (int j = 0; j < 4; ++j)
            #pragma unroll
            for (int r = 0; r < 4; ++r) acc[i][j][r] = 0.f;

    cp_tile(A, lda, m0, M, kbase, smBase + 0 * TILE_B, tid);
    cp_tile(B, ldb, n0, N, kbase, smBase + 1 * TILE_B, tid);
    if (NS == 3) {
        cp_tile(Al, lda, m0, M, kbase, smBase + 2 * TILE_B, tid);
        cp_tile(Bl, ldb, n0, N, kbase, smBase + 3 * TILE_B, tid);
    }
    CP_COMMIT();

    const int ra = lane & 15;
    const int rb = (lane >> 4) * 8;

    for (int c = 0; c < nc; ++c) {
        int nx = c + 1;
        if (nx < nc) {
            uint32_t sb = smBase + (uint32_t)((nx & 1) * nT) * TILE_B;
            int k0 = kbase + (nx << 5);
            cp_tile(A, lda, m0, M, k0, sb + 0 * TILE_B, tid);
            cp_tile(B, ldb, n0, N, k0, sb + 1 * TILE_B, tid);
            if (NS == 3) {
                cp_tile(Al, lda, m0, M, k0, sb + 2 * TILE_B, tid);
                cp_tile(Bl, ldb, n0, N, k0, sb + 3 * TILE_B, tid);
            }
            CP_COMMIT();
            CP_WAIT(1);
        } else {
            CP_WAIT(0);
        }
        __syncthreads();

        uint32_t sb = smBase + (uint32_t)((c & 1) * nT) * TILE_B;
        uint32_t aB = sb, bB = sb + TILE_B, alB = sb + 2 * TILE_B, blB = sb + 3 * TILE_B;

        #pragma unroll
        for (int ks = 0; ks < 32; ks += 16) {
            uint32_t ah[4][4], bh[2][4];
            #pragma unroll
            for (int mi = 0; mi < 4; ++mi)
                LDM4(ah[mi], aB + (uint32_t)((wm * 64 + mi * 16 + ra) * 80 + (ks + rb) * 2));
            #pragma unroll
            for (int nb = 0; nb < 2; ++nb)
                LDM4(bh[nb], bB + (uint32_t)((wn * 32 + nb * 16 + ra) * 80 + (ks + rb) * 2));
            if (NS == 3) {
                uint32_t al[4][4], bl[2][4];
                #pragma unroll
                for (int mi = 0; mi < 4; ++mi)
                    LDM4(al[mi], alB + (uint32_t)((wm * 64 + mi * 16 + ra) * 80 + (ks + rb) * 2));
                #pragma unroll
                for (int nb = 0; nb < 2; ++nb)
                    LDM4(bl[nb], blB + (uint32_t)((wn * 32 + nb * 16 + ra) * 80 + (ks + rb) * 2));
                #pragma unroll
                for (int mi = 0; mi < 4; ++mi)
                    #pragma unroll
                    for (int nj = 0; nj < 4; ++nj) {
                        int nb = nj >> 1, q = nj & 1;
                        MMA16816(acc[mi][nj], ah[mi], bh[nb][q], bh[nb][q + 2]);
                        MMA16816(acc[mi][nj], ah[mi], bl[nb][q], bl[nb][q + 2]);
                        MMA16816(acc[mi][nj], al[mi], bh[nb][q], bh[nb][q + 2]);
                    }
            } else {
                #pragma unroll
                for (int mi = 0; mi < 4; ++mi)
                    #pragma unroll
                    for (int nj = 0; nj < 4; ++nj) {
                        int nb = nj >> 1, q = nj & 1;
                        MMA16816(acc[mi][nj], ah[mi], bh[nb][q], bh[nb][q + 2]);
                    }
            }
        }
        __syncthreads();
    }

    float* Cz = (EPI == 1) ? (Cf + (size_t)blockIdx.z * zs) : Cf;
    const int g = lane >> 2, tq = lane & 3;
    #pragma unroll
    for (int mi = 0; mi < 4; ++mi) {
        int mA = m0 + wm * 64 + mi * 16 + g;
        int mB = mA + 8;
        float r2A = 0.f, r2B = 0.f;
        if (EPI == 2) {
            if (mA < M) r2A = aux2[mA];
            if (mB < M) r2B = aux2[mB];
        }
        #pragma unroll
        for (int nj = 0; nj < 4; ++nj) {
            int n = n0 + wn * 32 + nj * 8 + tq * 2;
            if (n >= N) continue;
            float c0 = acc[mi][nj][0], c1 = acc[mi][nj][1];
            float c2 = acc[mi][nj][2], c3 = acc[mi][nj][3];
            if (EPI == 1) {
                if (mA < M) *(float2*)(Cz + (size_t)mA * ldc + n) = make_float2(c0, c1);
                if (mB < M) *(float2*)(Cz + (size_t)mB * ldc + n) = make_float2(c2, c3);
            } else if (EPI == 0) {
                float a0 = aux1[n], a1 = aux1[n + 1];
                if (mA < M) *(float2*)(Cz + (size_t)mA * ldc + n) = make_float2(c0 + a0, c1 + a1);
                if (mB < M) *(float2*)(Cz + (size_t)mB * ldc + n) = make_float2(c2 + a0, c3 + a1);
            } else {  // EPI 2: region -> cat + hi/lo
                float a0 = aux1[n], a1 = aux1[n + 1];
                if (mA < M) {
                    float v0 = (c0 + a0) * r2A, v1 = (c1 + a1) * r2A;
                    size_t o = (size_t)mA * D3 + 128 + n;
                    *(float2*)(g_cat + o) = make_float2(v0, v1);
                    __nv_bfloat16 h0 = __float2bfloat16(v0), h1 = __float2bfloat16(v1);
                    *(uint32_t*)(g_ch + o) = pack_bf2(v0, v1);
                    *(uint32_t*)(g_cl + o) = pack_bf2(v0 - __bfloat162float(h0),
                                                      v1 - __bfloat162float(h1));
                }
                if (mB < M) {
                    float v2 = (c2 + a0) * r2B, v3 = (c3 + a1) * r2B;
                    size_t o = (size_t)mB * D3 + 128 + n;
                    *(float2*)(g_cat + o) = make_float2(v2, v3);
                    __nv_bfloat16 h2 = __float2bfloat16(v2), h3 = __float2bfloat16(v3);
                    *(uint32_t*)(g_ch + o) = pack_bf2(v2, v3);
                    *(uint32_t*)(g_cl + o) = pack_bf2(v2 - __bfloat162float(h2),
                                                      v3 - __bfloat162float(h3));
                }
            }
        }
    }
}

// ---------------- gram reduce: fold perm + /16 -> GsT bf16 ----------------
__global__ void gram_reduce_kernel() {                        // grid 256, block 256
    int ep = blockIdx.x, n = threadIdx.x;
    int e = (ep + 128) & 255;                                 // ep = (e+128)%256
    float s = 0.f;
    for (int z = 0; z < NCH; ++z)
        s += g_gpart[(size_t)z * (TWOD * TWOD) + ep * TWOD + n];   // coalesced over n
    g_GsT[n * TWOD + e] = __float2bfloat16(s * 0.0625f);
}

// ---------------- emb half of cat ----------------
__global__ void emb_cat_kernel(const float* __restrict__ eitem) {
    int idx = blockIdx.x * 256 + threadIdx.x;                 // over NI*128
    if (idx >= NI * 128) return;
    int i = idx >> 7, c = idx & 127;
    float v = eitem[idx];
    g_cat[(size_t)i * D3 + c] = v;
    __nv_bfloat16 h = __float2bfloat16(v);
    g_ch[(size_t)i * D3 + c] = h;
    g_cl[(size_t)i * D3 + c] = __float2bfloat16(v - __bfloat162float(h));
}

// ---------------- stacked weights ----------------
__global__ void build_w_kernel(const float* __restrict__ Wk, const float* __restrict__ Wv,
                               const float* __restrict__ Wq,
                               const float* __restrict__ bk, const float* __restrict__ bv,
                               const float* __restrict__ bq) {
    int idx = blockIdx.x * 256 + threadIdx.x;
    if (idx < NW * D3) {
        int r = idx / D3, c = idx - r * D3;
        float w = (r < D3) ? Wk[r * D3 + c]
                : (r < 2 * D3) ? Wv[(r - D3) * D3 + c]
                : Wq[(r - 2 * D3) * D3 + c];
        __nv_bfloat16 h = __float2bfloat16(w);
        g_wh[idx] = h;
        g_wl[idx] = __float2bfloat16(w - __bfloat162float(h));
    }
    if (idx < NW) {
        g_bias[idx] = (idx < D3) ? bk[idx]
                    : (idx < 2 * D3) ? bv[idx - D3]
                    : bq[idx - 2 * D3];
    }
}

// ---------------- final predictions ----------------
__global__ __launch_bounds__(128) void final_pred_kernel(
    const int* __restrict__ user, const int* __restrict__ item_i,
    const int* __restrict__ item_j, float* __restrict__ out)
{
    int b = blockIdx.x, t = threadIdx.x;
    __shared__ float qp[D3], qn[D3], tp[D3], tn[D3];
    __shared__ int   su[L_];
    __shared__ float wp[L_], wn[L_];
    __shared__ float red[128];
    __shared__ float sh_inv[2];

    const int ii = item_i[b], jj = item_j[b];
    if (t < L_) su[t] = user[b * L_ + t];
    for (int c = t; c < D3; c += 128) {
        qp[c] = g_kvq[(size_t)ii * NW + 2 * D3 + c];
        qn[c] = g_kvq[(size_t)jj * NW + 2 * D3 + c];
        tp[c] = g_cat[(size_t)ii * D3 + c];
        tn[c] = g_cat[(size_t)jj * D3 + c];
    }
    __syncthreads();

    if (t < L_) {
        float sp = 0.f, sn = 0.f;
        int li = 0, rem = t;
        #pragma unroll 4
        for (int d = 0; d < D3; ++d) {
            float kv = g_kvq[(size_t)su[li] * NW + rem];
            sp += qp[d] * kv;
            sn += qn[d] * kv;
            rem += L_;
            if (rem >= D3) { rem -= D3; ++li; }
        }
        const float invsc = 0.05103103630798287f;             // 1/sqrt(384)
        sp *= invsc; sn *= invsc;
        wp[t] = (su[t] != ii) ? __expf(sp) : 0.f;
        wn[t] = __expf(sn);
    }
    __syncthreads();

    red[t] = (t < L_) ? wp[t] : 0.f; __syncthreads();
    for (int o = 64; o > 0; o >>= 1) { if (t < o) red[t] += red[t + o]; __syncthreads(); }
    if (t == 0) sh_inv[0] = rsqrtf(red[0]);
    __syncthreads();
    red[t] = (t < L_) ? wn[t] : 0.f; __syncthreads();
    for (int o = 64; o > 0; o >>= 1) { if (t < o) red[t] += red[t + o]; __syncthreads(); }
    if (t == 0) sh_inv[1] = rsqrtf(red[0]);
    __syncthreads();
    if (t < L_) { wp[t] *= sh_inv[0]; wn[t] *= sh_inv[1]; }
    __syncthreads();

    float pP = 0.f, pN = 0.f;
    #pragma unroll
    for (int ch = 0; ch < 3; ++ch) {
        int d = ch * 128 + t;
        float aP = 0.f, aN = 0.f;
        #pragma unroll 4
        for (int l = 0; l < L_; ++l) {
            float v = g_kvq[(size_t)su[l] * NW + D3 + d];
            aP += wp[l] * v;
            aN += wn[l] * v;
        }
        pP += aP * tp[d];
        pN += aN * tn[d];
    }
    red[t] = pP; __syncthreads();
    for (int o = 64; o > 0; o >>= 1) { if (t < o) red[t] += red[t + o]; __syncthreads(); }
    if (t == 0) out[b] = red[0];
    __syncthreads();
    red[t] = pN; __syncthreads();
    for (int o = 64; o > 0; o >>= 1) { if (t < o) red[t] += red[t + o]; __syncthreads(); }
    if (t == 0) out[B_ + b] = red[0];
}

// ---------------- launch ----------------
extern "C" void kernel_launch(void* const* d_in, const int* in_sizes, int n_in,
                              void* d_out, int out_size) {
    const int*   user     = (const int*)  d_in[0];
    const int*   item_i   = (const int*)  d_in[1];
    const int*   item_j   = (const int*)  d_in[2];
    const float* emb_item = (const float*)d_in[3];
    const float* emb_in   = (const float*)d_in[4];
    const float* emb_out  = (const float*)d_in[5];
    const float* Wq       = (const float*)d_in[6];
    const float* bq       = (const float*)d_in[7];
    const float* Wk       = (const float*)d_in[8];
    const float* bk       = (const float*)d_in[9];
    const float* Wv       = (const float*)d_in[10];
    const float* bv       = (const float*)d_in[11];
    float* out = (float*)d_out;

    __nv_bfloat16 *qb, *qT, *GsT, *ch, *cl, *wh, *wl;
    float *gpart, *colsum, *rs, *kvq, *bias;
    cudaGetSymbolAddress((void**)&qb,     g_qb);
    cudaGetSymbolAddress((void**)&qT,     g_qT);
    cudaGetSymbolAddress((void**)&GsT,    g_GsT);
    cudaGetSymbolAddress((void**)&ch,     g_ch);
    cudaGetSymbolAddress((void**)&cl,     g_cl);
    cudaGetSymbolAddress((void**)&wh,     g_wh);
    cudaGetSymbolAddress((void**)&wl,     g_wl);
    cudaGetSymbolAddress((void**)&gpart,  g_gpart);
    cudaGetSymbolAddress((void**)&colsum, g_colsum);
    cudaGetSymbolAddress((void**)&rs,     g_rs);
    cudaGetSymbolAddress((void**)&kvq,    g_kvq);
    cudaGetSymbolAddress((void**)&bias,   g_bias);

    const int SMEM_1 = 4 * TILE_B;   // 40960
    const int SMEM_3 = 8 * TILE_B;   // 81920
    cudaFuncSetAttribute(mma_gemm<0, 3>, cudaFuncAttributeMaxDynamicSharedMemorySize, SMEM_3);
    cudaFuncSetAttribute(mma_gemm<1, 1>, cudaFuncAttributeMaxDynamicSharedMemorySize, SMEM_1);
    cudaFuncSetAttribute(mma_gemm<2, 1>, cudaFuncAttributeMaxDynamicSharedMemorySize, SMEM_1);

    // 1. qb bf16 + qT bf16 (padded transpose)
    build_qb_kernel<<<(NI * 128) / 256, 256>>>(emb_in, emb_out);
    qT_kernel<<<dim3(KP2 / 32, TWOD / 32), dim3(32, 8)>>>(emb_in, emb_out);
    // 2. exact column sums
    colsum_part_kernel<<<NCH, 256>>>(emb_in, emb_out);
    colsum_fin_kernel<<<1, 256>>>();
    // 3. denominators
    rs_kernel<<<1250, 256>>>(emb_in, emb_out);
    // 4. Gram = qT . qT^T (tensor, split-K 40) -> partials
    mma_gemm<1, 1><<<dim3(2, 2, NCH), 256, SMEM_1>>>(
        TWOD, TWOD, KP2, KP2 / NCH, qT, nullptr, KP2, qT, nullptr, KP2,
        gpart, TWOD, (size_t)(TWOD * TWOD), nullptr, nullptr);
    // 5. reduce partials, fold permutation + /16 -> GsT bf16
    gram_reduce_kernel<<<TWOD, 256>>>();
    // 6. region = (colsum + q.Gs) * rs -> cat[:,128:384] + hi/lo (tensor)
    mma_gemm<2, 1><<<dim3(2, (NI + 127) / 128), 256, SMEM_1>>>(
        NI, TWOD, TWOD, TWOD, qb, nullptr, TWOD, GsT, nullptr, TWOD,
        nullptr, 0, 0, colsum, rs);
    // 7. emb half of cat + weights
    emb_cat_kernel<<<(NI * 128) / 256, 256>>>(emb_item);
    build_w_kernel<<<(NW * D3 + 255) / 256, 256>>>(Wk, Wv, Wq, bk, bv, bq);
    // 8. KVQ table [10000, 1152] (tensor, split-3)
    mma_gemm<0, 3><<<dim3(NW / 128, (NI + 127) / 128), 256, SMEM_3>>>(
        NI, NW, D3, D3, ch, cl, D3, wh, wl, D3,
        kvq, NW, 0, bias, nullptr);
    // 9. final predictions
    final_pred_kernel<<<B_, 128>>>(user, item_i, item_j, out);
}